// round 9
// baseline (speedup 1.0000x reference)
#include <cuda_runtime.h>
#include <cstdint>

#define N_NODES     200000
#define N_CLS       10
#define IDS_PER_CLS 20000
#define CENTER_BUDGET 2000
#define HOP_BUDGET  16384
#define CAND_CAP    16384
#define CCAP        4096
#define GRID        148
#define TPB         1024
#define NTH         (GRID * TPB)
#define GS          16

struct Ctrl { unsigned cand_n, need2, thrT, take_all; };

__device__ Ctrl               g_ctrl;
__device__ unsigned           g_cnt[GS];    // zero-init; self-resetting
__device__ unsigned           g_flag[GS];   // zero-init; monotonic across replays
__device__ float              g_probs[N_NODES];
__device__ unsigned long long g_keys[N_NODES];
__device__ unsigned char      g_center[N_NODES];
__device__ unsigned char      g_retained[N_NODES];
__device__ unsigned char      g_nbr[N_NODES];
__device__ unsigned           g_hist[65536];
__device__ unsigned long long g_cand[CAND_CAP];
__device__ int                g_center_nodes[N_CLS * CENTER_BUDGET];

// ---------------------------------------------------------------------------
// threefry2x32 — matches JAX bit-for-bit (partitionable mode; validated)
// ---------------------------------------------------------------------------
__device__ __forceinline__ void tf2x32(unsigned k0, unsigned k1,
                                       unsigned x0, unsigned x1,
                                       unsigned &o0, unsigned &o1) {
  unsigned ks2 = k0 ^ k1 ^ 0x1BD11BDAu;
  x0 += k0; x1 += k1;
#define TFR(r) { x0 += x1; x1 = (x1 << (r)) | (x1 >> (32 - (r))); x1 ^= x0; }
  TFR(13) TFR(15) TFR(26) TFR(6)
  x0 += k1;  x1 += ks2 + 1u;
  TFR(17) TFR(29) TFR(16) TFR(24)
  x0 += ks2; x1 += k0 + 2u;
  TFR(13) TFR(15) TFR(26) TFR(6)
  x0 += k0;  x1 += k1 + 3u;
  TFR(17) TFR(29) TFR(16) TFR(24)
  x0 += k1;  x1 += ks2 + 4u;
  TFR(13) TFR(15) TFR(26) TFR(6)
  x0 += ks2; x1 += k0 + 5u;
#undef TFR
  o0 = x0; o1 = x1;
}
__device__ __forceinline__ unsigned pbits32(unsigned k0, unsigned k1, unsigned i) {
  unsigned o0, o1; tf2x32(k0, k1, 0u, i, o0, o1); return o0 ^ o1;
}
__device__ __forceinline__ unsigned long long pbits64(unsigned k0, unsigned k1, unsigned i) {
  unsigned o0, o1; tf2x32(k0, k1, 0u, i, o0, o1);
  return (((unsigned long long)o0) << 32) | o1;
}

// ---------------------------------------------------------------------------
// Replay-safe grid barrier (sense via monotonic flag; counter self-resets).
// All GRID blocks co-resident (GRID <= #SMs) => no deadlock.
// ---------------------------------------------------------------------------
__device__ __forceinline__ void gsync(int i) {
  __syncthreads();
  if (threadIdx.x == 0) {
    __threadfence();
    unsigned f0 = atomicAdd(&g_flag[i], 0u);
    __threadfence();
    if (atomicAdd(&g_cnt[i], 1u) == GRID - 1u) {
      g_cnt[i] = 0u;
      __threadfence();
      atomicAdd(&g_flag[i], 1u);
    } else {
      while (atomicAdd(&g_flag[i], 0u) == f0) __nanosleep(64);
    }
    __threadfence();
  }
  __syncthreads();
}

extern __shared__ unsigned char s_raw[];

// ---------------------------------------------------------------------------
// THE kernel: all phases in one launch.
// smem carve: [0,32K) u64 skey | [32K,48K) u32 sjdx/hist2 | [48K,64K) u32 hist
//             [64K,68K) u32 part | [68K,93K) u32 center bitmask (6250 words)
// ---------------------------------------------------------------------------
__global__ __launch_bounds__(TPB, 1) void k_all(const void* edge, const float* w,
                                                long long E, float* out,
                                                long long out_size) {
  unsigned long long* sA   = (unsigned long long*)s_raw;            // 32KB
  unsigned*           sB   = (unsigned*)(s_raw + 32768);            // 16KB
  unsigned*           sC   = (unsigned*)(s_raw + 49152);            // 16KB
  unsigned*           part = (unsigned*)(s_raw + 65536);            // 4KB
  unsigned*           sMask= (unsigned*)(s_raw + 69632);            // 25KB
  __shared__ int      s_bad, s_T;
  __shared__ unsigned s_cnt, s_scnt, s_need3;
  __shared__ int      s_T2;

  const int tid = threadIdx.x;
  const int bid = blockIdx.x;
  const int gt  = bid * TPB + tid;

  // ---- per-block dtype probe + per-thread key material ----
  if (tid == 0) s_bad = 0;
  __syncthreads();
  {
    long long lim = (E < 128) ? E : 128;
    if (tid < 128 && (long long)tid < lim) {
      long long v = ((const long long*)edge)[tid];
      if (v < 0 || v >= N_NODES) atomicOr(&s_bad, 1);
    }
  }
  unsigned kc0, kc1, kA0, kA1, kB0, kB1;
  tf2x32(0u, 42u, 0u, 0u, kc0, kc1);   // k_cls
  tf2x32(0u, 42u, 0u, 1u, kA0, kA1);   // k_h1
  tf2x32(0u, 42u, 0u, 2u, kB0, kB1);   // k_h2
  __syncthreads();
  const int is64 = s_bad ? 0 : 1;

  // ================= P0: zero state =================
  for (int i = gt; i < N_NODES; i += NTH) {
    g_probs[i] = 0.f; g_center[i] = 0; g_retained[i] = 0; g_nbr[i] = 0;
  }
  for (int i = gt; i < 65536; i += NTH) g_hist[i] = 0;
  if (gt == 0) g_ctrl.cand_n = 0;
  gsync(0);

  // ================= centers (blocks 0..9, one class each) =================
  if (bid < N_CLS) {
    const int c = bid, base = c * IDS_PER_CLS;
    for (int b = tid; b < CCAP; b += TPB) sC[b] = 0;
    if (tid == 0) s_cnt = 0;
    __syncthreads();

    for (int j = tid; j < IDS_PER_CLS; j += TPB) {
      unsigned m = (unsigned)(base + j);
      unsigned long long key; unsigned b;
      if (is64) {
        unsigned long long mant = pbits64(kc0, kc1, m) >> 12;  // u = mant*2^-52
        key = mant; b = (unsigned)(mant >> 40);
      } else {
        unsigned man = pbits32(kc0, kc1, m) >> 9;              // u = man*2^-23
        key = (((unsigned long long)man) << 32) | (unsigned)j;
        b = man >> 11;
      }
      g_keys[m] = key;
      atomicAdd(&sC[b], 1u);
    }
    __syncthreads();

    // ascending threshold via prefix scan (4 buckets/thread)
    unsigned mysum = 0;
    for (int b = tid * 4; b < tid * 4 + 4; b++) mysum += sC[b];
    part[tid] = mysum; __syncthreads();
    for (int off = 1; off < TPB; off <<= 1) {
      unsigned v = part[tid];
      if (tid >= off) v += part[tid - off];
      __syncthreads(); part[tid] = v; __syncthreads();
    }
    unsigned P = part[tid];
    if (P >= CENTER_BUDGET && P - mysum < CENTER_BUDGET) {
      unsigned acc = P - mysum; int T = tid * 4 + 3;
      for (int b = tid * 4; b < tid * 4 + 4; b++) {
        acc += sC[b];
        if (acc >= CENTER_BUDGET) { T = b; break; }
      }
      s_T = T;
    }
    __syncthreads();
    int T = s_T;

    for (int j = tid; j < IDS_PER_CLS; j += TPB) {
      int m = base + j;
      unsigned long long key = g_keys[m];
      unsigned b = is64 ? (unsigned)(key >> 40) : (unsigned)(key >> 43);
      if ((int)b <= T) {
        unsigned pos = atomicAdd(&s_cnt, 1u);
        if (pos < CCAP) { sA[pos] = key; sB[pos] = (unsigned)j; }
      }
    }
    __syncthreads();
    int cnt = (int)((s_cnt < CCAP) ? s_cnt : CCAP);

    for (int p = tid; p < cnt; p += TPB) {
      unsigned long long k = sA[p];
      unsigned j = sB[p];
      int rank = 0;
      for (int i = 0; i < cnt; i++) {
        unsigned long long ki = sA[i];
        unsigned ji = sB[i];
        rank += (ki < k) || (ki == k && ji < j);
      }
      if (rank < CENTER_BUDGET) {
        int node = base + (int)j;
        g_center_nodes[c * CENTER_BUDGET + rank] = node;
        g_center[node] = 1;
        g_retained[node] = 1;
      }
    }
  }
  gsync(1);

  // ================= edge pass (center bitmask in smem) =================
  for (int wd = tid; wd < (N_NODES + 31) / 32; wd += TPB) {
    unsigned m = 0;
    int nb = N_NODES - wd * 32; if (nb > 32) nb = 32;
    for (int b = 0; b < nb; b++) m |= ((unsigned)g_center[wd * 32 + b]) << b;
    sMask[wd] = m;
  }
  __syncthreads();
  {
    long long chunk = (((E + GRID - 1) / GRID) + 3) & ~3LL;
    long long lo = (long long)bid * chunk;
    long long hi = lo + chunk; if (hi > E) hi = E;
    bool vec = is64 ? ((E & 1) == 0) : ((E & 3) == 0);
    for (long long i = lo + (long long)tid * 4; i < hi; i += (long long)TPB * 4) {
      if (vec && i + 3 < hi) {
        int s[4], d[4];
        if (is64) {
          const ulonglong2* ps = (const ulonglong2*)((const long long*)edge + i);
          const ulonglong2* pd = (const ulonglong2*)((const long long*)edge + E + i);
          ulonglong2 s01 = ps[0], s23 = ps[1], d01 = pd[0], d23 = pd[1];
          s[0]=(int)s01.x; s[1]=(int)s01.y; s[2]=(int)s23.x; s[3]=(int)s23.y;
          d[0]=(int)d01.x; d[1]=(int)d01.y; d[2]=(int)d23.x; d[3]=(int)d23.y;
        } else {
          int4 sv = *(const int4*)((const int*)edge + i);
          int4 dv = *(const int4*)((const int*)edge + E + i);
          s[0]=sv.x; s[1]=sv.y; s[2]=sv.z; s[3]=sv.w;
          d[0]=dv.x; d[1]=dv.y; d[2]=dv.z; d[3]=dv.w;
        }
        float4 wv = *(const float4*)(w + i);
        atomicAdd(&g_probs[d[0]], wv.x);
        atomicAdd(&g_probs[d[1]], wv.y);
        atomicAdd(&g_probs[d[2]], wv.z);
        atomicAdd(&g_probs[d[3]], wv.w);
        #pragma unroll
        for (int q = 0; q < 4; q++)
          if ((sMask[s[q] >> 5] >> (s[q] & 31)) & 1u) g_nbr[d[q]] = 1;
      } else {
        for (long long t = i; t < hi && t < i + 4; t++) {
          int s, d;
          if (is64) {
            s = (int)((const long long*)edge)[t];
            d = (int)((const long long*)edge)[E + t];
          } else {
            s = ((const int*)edge)[t];
            d = ((const int*)edge)[E + t];
          }
          atomicAdd(&g_probs[d], w[t]);
          if ((sMask[s >> 5] >> (s & 31)) & 1u) g_nbr[d] = 1;
        }
      }
    }
  }
  gsync(2);

  // ================= two hops =================
  for (int h = 0; h < 2; h++) {
    unsigned kh0 = h ? kB0 : kA0, kh1 = h ? kB1 : kA1;

    // ---- build keys (candidate-skip; bit-exact gumbel) ----
    for (int n = gt; n < N_NODES; n += NTH) {
      unsigned long long kk = 0;
      if (g_nbr[n] && !g_retained[n]) {
        unsigned bits = pbits32(kh0, kh1, (unsigned)n);
        float ur = __uint_as_float((bits >> 9) | 0x3f800000u) - 1.0f;
        float u  = fmaxf(1.17549435e-38f, ur + 1.17549435e-38f);
        float g  = -logf(-logf(u));
        float v  = logf(g_probs[n]) + g;
        if (isfinite(v)) {
          unsigned b   = __float_as_uint(v);
          unsigned ord = b ^ ((b & 0x80000000u) ? 0xFFFFFFFFu : 0x80000000u);
          kk = (((unsigned long long)ord) << 32) | (0xFFFFFFFFu - (unsigned)n);
          atomicAdd(&g_hist[(unsigned)(kk >> 48)], 1u);
        }
      }
      g_keys[n] = kk;
    }
    gsync(3 + h * 4);

    // ---- threshold (block 0): suffix scan over 65536 digits ----
    if (bid == 0) {
      unsigned mysum = 0;
      #pragma unroll 8
      for (int b = tid * 64; b < tid * 64 + 64; b++) mysum += g_hist[b];
      part[tid] = mysum; __syncthreads();
      for (int off = 1; off < TPB; off <<= 1) {
        unsigned v = part[tid];
        if (tid + off < TPB) v += part[tid + off];
        __syncthreads(); part[tid] = v; __syncthreads();
      }
      unsigned total = part[0];
      unsigned need = (total < HOP_BUDGET) ? total : HOP_BUDGET;
      if (tid == 0 && need == 0) {
        g_ctrl.thrT = 0xFFFFFFFFu; g_ctrl.need2 = 0; g_ctrl.take_all = 0;
        g_ctrl.cand_n = 0;
      }
      if (need != 0) {
        unsigned S = part[tid];
        if (S >= need && S - mysum < need) {
          unsigned acc = S - mysum;
          for (int b = tid * 64 + 63; b >= tid * 64; b--) {
            unsigned hb = g_hist[b];
            if (acc + hb >= need) {
              g_ctrl.thrT = (unsigned)b;
              unsigned need2 = need - acc;
              g_ctrl.need2 = need2;
              g_ctrl.take_all = (need2 >= hb) ? 1u : 0u;
              g_ctrl.cand_n = 0;
              break;
            }
            acc += hb;
          }
        }
      }
    }
    gsync(4 + h * 4);

    // ---- scatter winners + collect boundary; re-zero hist ----
    {
      unsigned T = g_ctrl.thrT;
      unsigned take_all = g_ctrl.take_all;
      for (int n = gt; n < 65536; n += NTH) g_hist[n] = 0;
      for (int n = gt; n < N_NODES; n += NTH) {
        unsigned long long kk = g_keys[n];
        if (kk) {
          unsigned dg = (unsigned)(kk >> 48);
          if (dg > T) {
            g_retained[n] = 1;
          } else if (dg == T) {
            if (take_all) {
              g_retained[n] = 1;
            } else {
              unsigned pos = atomicAdd(&g_ctrl.cand_n, 1u);
              if (pos < CAND_CAP) g_cand[pos] = kk;
            }
          }
        }
      }
    }
    gsync(5 + h * 4);

    // ---- boundary refine (block 0): level-2 hist (bits 47:36) + rank ----
    if (bid == 0) {
      unsigned take_all = g_ctrl.take_all;
      unsigned need2 = g_ctrl.need2;
      if (!take_all && need2 != 0) {
        unsigned cn = g_ctrl.cand_n;
        int cnt = (int)((cn < CAND_CAP) ? cn : CAND_CAP);
        for (int b = tid; b < 4096; b += TPB) sB[b] = 0;
        if (tid == 0) s_scnt = 0;
        __syncthreads();
        for (int i = tid; i < cnt; i += TPB)
          atomicAdd(&sB[(unsigned)(g_cand[i] >> 36) & 0xFFFu], 1u);
        __syncthreads();

        unsigned mysum = 0;
        for (int b = tid * 4; b < tid * 4 + 4; b++) mysum += sB[b];
        part[tid] = mysum; __syncthreads();
        for (int off = 1; off < TPB; off <<= 1) {
          unsigned v = part[tid];
          if (tid + off < TPB) v += part[tid + off];
          __syncthreads(); part[tid] = v; __syncthreads();
        }
        unsigned S = part[tid];
        if (S >= need2 && S - mysum < need2) {
          unsigned acc = S - mysum; int T2 = tid * 4; unsigned n3 = need2;
          for (int b = tid * 4 + 3; b >= tid * 4; b--) {
            unsigned hb = sB[b];
            if (acc + hb >= need2) { T2 = b; n3 = need2 - acc; break; }
            acc += hb;
          }
          s_T2 = T2; s_need3 = n3;
        }
        __syncthreads();
        int T2 = s_T2;
        unsigned need3 = s_need3;

        for (int i = tid; i < cnt; i += TPB) {
          unsigned long long k = g_cand[i];
          int d2 = (int)((k >> 36) & 0xFFFu);
          if (d2 > T2) {
            g_retained[0xFFFFFFFFu - (unsigned)(k & 0xFFFFFFFFu)] = 1;
          } else if (d2 == T2) {
            unsigned p = atomicAdd(&s_scnt, 1u);
            if (p < 4096) sA[p] = k;
          }
        }
        __syncthreads();
        int c2 = (int)((s_scnt < 4096u) ? s_scnt : 4096u);
        for (int p = tid; p < c2; p += TPB) {
          unsigned long long myk = sA[p];
          int rank = 0;
          for (int i = 0; i < c2; i++) rank += (sA[i] > myk);
          if (rank < (int)need3)
            g_retained[0xFFFFFFFFu - (unsigned)(myk & 0xFFFFFFFFu)] = 1;
        }
      }
    }
    gsync(6 + h * 4);
  }

  // ================= output =================
  for (long long i = gt; i < out_size; i += NTH) {
    float v;
    if (out_size == 420000) {
      if (i < 20000)        v = (float)g_center_nodes[i];
      else if (i < 220000)  v = g_retained[i - 20000] ? 1.f : 0.f;
      else                  v = g_retained[i - 220000] ? g_probs[i - 220000] : 0.f;
    } else if (out_size == 400000) {
      if (i < 200000)       v = g_retained[i] ? 1.f : 0.f;
      else                  v = g_retained[i - 200000] ? g_probs[i - 200000] : 0.f;
    } else if (out_size == 200000) {
      v = g_retained[i] ? g_probs[i] : 0.f;
    } else if (out_size == 20000) {
      v = (float)g_center_nodes[i];
    } else {
      v = 0.f;
    }
    out[i] = v;
  }
}

// ---------------------------------------------------------------------------
extern "C" void kernel_launch(void* const* d_in, const int* in_sizes, int n_in,
                              void* d_out, int out_size) {
  const void* edge = d_in[0];
  const float* w = (const float*)d_in[1];
  long long E = (long long)in_sizes[0] / 2;

  static int smem_set = 0;
  const int SMEM = 69632 + 25008;    // carve regions + mask
  if (!smem_set) {
    cudaFuncSetAttribute(k_all, cudaFuncAttributeMaxDynamicSharedMemorySize, SMEM);
    smem_set = 1;
  }
  k_all<<<GRID, TPB, SMEM>>>(edge, w, E, (float*)d_out, (long long)out_size);
}

// round 10
// speedup vs baseline: 1.0074x; 1.0074x over previous
#include <cuda_runtime.h>
#include <cstdint>

#define N_NODES     200000
#define N_CLS       10
#define IDS_PER_CLS 20000
#define CENTER_BUDGET 2000
#define HOP_BUDGET  16384
#define CAND_CAP    16384
#define CCAP        4096
#define GRID        148
#define TPB         1024
#define NTH         (GRID * TPB)
#define GS          16

struct Ctrl { unsigned cand_n, need2, thrT, take_all; };

__device__ Ctrl               g_ctrl;
__device__ unsigned           g_cnt[GS];    // zero-init; self-resetting
__device__ unsigned           g_flag[GS];   // zero-init; monotonic across replays
__device__ float              g_probs[N_NODES];
__device__ unsigned long long g_keys[N_NODES];
__device__ unsigned char      g_center[N_NODES];
__device__ unsigned char      g_retained[N_NODES];
__device__ unsigned char      g_nbr[N_NODES];
__device__ unsigned           g_hist[65536];
__device__ unsigned long long g_cand[CAND_CAP];
__device__ int                g_center_nodes[N_CLS * CENTER_BUDGET];

// ---------------------------------------------------------------------------
// threefry2x32 — matches JAX bit-for-bit (partitionable mode; validated)
// ---------------------------------------------------------------------------
__device__ __forceinline__ void tf2x32(unsigned k0, unsigned k1,
                                       unsigned x0, unsigned x1,
                                       unsigned &o0, unsigned &o1) {
  unsigned ks2 = k0 ^ k1 ^ 0x1BD11BDAu;
  x0 += k0; x1 += k1;
#define TFR(r) { x0 += x1; x1 = (x1 << (r)) | (x1 >> (32 - (r))); x1 ^= x0; }
  TFR(13) TFR(15) TFR(26) TFR(6)
  x0 += k1;  x1 += ks2 + 1u;
  TFR(17) TFR(29) TFR(16) TFR(24)
  x0 += ks2; x1 += k0 + 2u;
  TFR(13) TFR(15) TFR(26) TFR(6)
  x0 += k0;  x1 += k1 + 3u;
  TFR(17) TFR(29) TFR(16) TFR(24)
  x0 += k1;  x1 += ks2 + 4u;
  TFR(13) TFR(15) TFR(26) TFR(6)
  x0 += ks2; x1 += k0 + 5u;
#undef TFR
  o0 = x0; o1 = x1;
}
__device__ __forceinline__ unsigned pbits32(unsigned k0, unsigned k1, unsigned i) {
  unsigned o0, o1; tf2x32(k0, k1, 0u, i, o0, o1); return o0 ^ o1;
}
__device__ __forceinline__ unsigned long long pbits64(unsigned k0, unsigned k1, unsigned i) {
  unsigned o0, o1; tf2x32(k0, k1, 0u, i, o0, o1);
  return (((unsigned long long)o0) << 32) | o1;
}

// ---------------------------------------------------------------------------
// Replay-safe grid barrier (sense via monotonic flag; counter self-resets).
// ---------------------------------------------------------------------------
__device__ __forceinline__ void gsync(int i) {
  __syncthreads();
  if (threadIdx.x == 0) {
    __threadfence();
    unsigned f0 = atomicAdd(&g_flag[i], 0u);
    __threadfence();
    if (atomicAdd(&g_cnt[i], 1u) == GRID - 1u) {
      g_cnt[i] = 0u;
      __threadfence();
      atomicAdd(&g_flag[i], 1u);
    } else {
      while (atomicAdd(&g_flag[i], 0u) == f0) __nanosleep(64);
    }
    __threadfence();
  }
  __syncthreads();
}

extern __shared__ unsigned char s_raw[];

// ---------------------------------------------------------------------------
__global__ __launch_bounds__(TPB, 1) void k_all(const void* __restrict__ edge,
                                                const float* __restrict__ w,
                                                long long E, float* __restrict__ out,
                                                long long out_size) {
  unsigned long long* sA   = (unsigned long long*)s_raw;            // 32KB
  unsigned*           sB   = (unsigned*)(s_raw + 32768);            // 16KB
  unsigned*           sC   = (unsigned*)(s_raw + 49152);            // 16KB
  unsigned*           part = (unsigned*)(s_raw + 65536);            // 4KB
  unsigned*           sMask= (unsigned*)(s_raw + 69632);            // 25KB
  __shared__ int      s_bad, s_T;
  __shared__ unsigned s_cnt, s_scnt, s_need3;
  __shared__ int      s_T2;

  const int tid = threadIdx.x;
  const int bid = blockIdx.x;
  const int gt  = bid * TPB + tid;

  // ---- per-block dtype probe + per-thread key material ----
  if (tid == 0) s_bad = 0;
  __syncthreads();
  {
    long long lim = (E < 128) ? E : 128;
    if (tid < 128 && (long long)tid < lim) {
      long long v = ((const long long*)edge)[tid];
      if (v < 0 || v >= N_NODES) atomicOr(&s_bad, 1);
    }
  }
  unsigned kc0, kc1, kA0, kA1, kB0, kB1;
  tf2x32(0u, 42u, 0u, 0u, kc0, kc1);   // k_cls
  tf2x32(0u, 42u, 0u, 1u, kA0, kA1);   // k_h1
  tf2x32(0u, 42u, 0u, 2u, kB0, kB1);   // k_h2
  __syncthreads();
  const int is64 = s_bad ? 0 : 1;

  // ================= P0: zero state =================
  for (int i = gt; i < N_NODES; i += NTH) {
    g_probs[i] = 0.f; g_center[i] = 0; g_retained[i] = 0; g_nbr[i] = 0;
  }
  for (int i = gt; i < 65536; i += NTH) g_hist[i] = 0;
  if (gt == 0) g_ctrl.cand_n = 0;
  gsync(0);

  // ================= centers (blocks 0..9, one class each) =================
  if (bid < N_CLS) {
    const int c = bid, base = c * IDS_PER_CLS;
    for (int b = tid; b < CCAP; b += TPB) sC[b] = 0;
    if (tid == 0) s_cnt = 0;
    __syncthreads();

    for (int j = tid; j < IDS_PER_CLS; j += TPB) {
      unsigned m = (unsigned)(base + j);
      unsigned long long key; unsigned b;
      if (is64) {
        unsigned long long mant = pbits64(kc0, kc1, m) >> 12;  // u = mant*2^-52
        key = mant; b = (unsigned)(mant >> 40);
      } else {
        unsigned man = pbits32(kc0, kc1, m) >> 9;              // u = man*2^-23
        key = (((unsigned long long)man) << 32) | (unsigned)j;
        b = man >> 11;
      }
      g_keys[m] = key;
      atomicAdd(&sC[b], 1u);
    }
    __syncthreads();

    unsigned mysum = 0;
    for (int b = tid * 4; b < tid * 4 + 4; b++) mysum += sC[b];
    part[tid] = mysum; __syncthreads();
    for (int off = 1; off < TPB; off <<= 1) {
      unsigned v = part[tid];
      if (tid >= off) v += part[tid - off];
      __syncthreads(); part[tid] = v; __syncthreads();
    }
    unsigned P = part[tid];
    if (P >= CENTER_BUDGET && P - mysum < CENTER_BUDGET) {
      unsigned acc = P - mysum; int T = tid * 4 + 3;
      for (int b = tid * 4; b < tid * 4 + 4; b++) {
        acc += sC[b];
        if (acc >= CENTER_BUDGET) { T = b; break; }
      }
      s_T = T;
    }
    __syncthreads();
    int T = s_T;

    for (int j = tid; j < IDS_PER_CLS; j += TPB) {
      int m = base + j;
      unsigned long long key = g_keys[m];
      unsigned b = is64 ? (unsigned)(key >> 40) : (unsigned)(key >> 43);
      if ((int)b <= T) {
        unsigned pos = atomicAdd(&s_cnt, 1u);
        if (pos < CCAP) { sA[pos] = key; sB[pos] = (unsigned)j; }
      }
    }
    __syncthreads();
    int cnt = (int)((s_cnt < CCAP) ? s_cnt : CCAP);

    for (int p = tid; p < cnt; p += TPB) {
      unsigned long long k = sA[p];
      unsigned j = sB[p];
      int rank = 0;
      for (int i = 0; i < cnt; i++) {
        unsigned long long ki = sA[i];
        unsigned ji = sB[i];
        rank += (ki < k) || (ki == k && ji < j);
      }
      if (rank < CENTER_BUDGET) {
        int node = base + (int)j;
        g_center_nodes[c * CENTER_BUDGET + rank] = node;
        g_center[node] = 1;
        g_retained[node] = 1;
      }
    }
  }
  gsync(1);

  // ================= edge pass: 8 edges/thread/iter, loads-then-atomics ====
  for (int wd = tid; wd < (N_NODES + 31) / 32; wd += TPB) {
    unsigned m = 0;
    int nb = N_NODES - wd * 32; if (nb > 32) nb = 32;
    for (int b = 0; b < nb; b++) m |= ((unsigned)g_center[wd * 32 + b]) << b;
    sMask[wd] = m;
  }
  __syncthreads();
  {
    long long chunk = (((E + GRID - 1) / GRID) + 7) & ~7LL;
    long long lo = (long long)bid * chunk;
    long long hi = lo + chunk; if (hi > E) hi = E;
    bool vec = is64 ? ((E & 1) == 0) : ((E & 3) == 0);
    for (long long i = lo + (long long)tid * 8; i < hi; i += (long long)TPB * 8) {
      if (vec && i + 8 <= hi) {
        int s[8], d[8];
        float wv[8];
        // ---- issue ALL loads first (10 independent 16B LDGs) ----
        if (is64) {
          const ulonglong2* ps = (const ulonglong2*)((const long long*)edge + i);
          const ulonglong2* pd = (const ulonglong2*)((const long long*)edge + E + i);
          ulonglong2 s01 = ps[0], s23 = ps[1], s45 = ps[2], s67 = ps[3];
          ulonglong2 d01 = pd[0], d23 = pd[1], d45 = pd[2], d67 = pd[3];
          float4 w0 = *(const float4*)(w + i);
          float4 w1 = *(const float4*)(w + i + 4);
          s[0]=(int)s01.x; s[1]=(int)s01.y; s[2]=(int)s23.x; s[3]=(int)s23.y;
          s[4]=(int)s45.x; s[5]=(int)s45.y; s[6]=(int)s67.x; s[7]=(int)s67.y;
          d[0]=(int)d01.x; d[1]=(int)d01.y; d[2]=(int)d23.x; d[3]=(int)d23.y;
          d[4]=(int)d45.x; d[5]=(int)d45.y; d[6]=(int)d67.x; d[7]=(int)d67.y;
          wv[0]=w0.x; wv[1]=w0.y; wv[2]=w0.z; wv[3]=w0.w;
          wv[4]=w1.x; wv[5]=w1.y; wv[6]=w1.z; wv[7]=w1.w;
        } else {
          const int4* ps = (const int4*)((const int*)edge + i);
          const int4* pd = (const int4*)((const int*)edge + E + i);
          int4 sv0 = ps[0], sv1 = ps[1];
          int4 dv0 = pd[0], dv1 = pd[1];
          float4 w0 = *(const float4*)(w + i);
          float4 w1 = *(const float4*)(w + i + 4);
          s[0]=sv0.x; s[1]=sv0.y; s[2]=sv0.z; s[3]=sv0.w;
          s[4]=sv1.x; s[5]=sv1.y; s[6]=sv1.z; s[7]=sv1.w;
          d[0]=dv0.x; d[1]=dv0.y; d[2]=dv0.z; d[3]=dv0.w;
          d[4]=dv1.x; d[5]=dv1.y; d[6]=dv1.z; d[7]=dv1.w;
          wv[0]=w0.x; wv[1]=w0.y; wv[2]=w0.z; wv[3]=w0.w;
          wv[4]=w1.x; wv[5]=w1.y; wv[6]=w1.z; wv[7]=w1.w;
        }
        // ---- then atomics + mask probes ----
        #pragma unroll
        for (int q = 0; q < 8; q++) atomicAdd(&g_probs[d[q]], wv[q]);
        #pragma unroll
        for (int q = 0; q < 8; q++)
          if ((sMask[s[q] >> 5] >> (s[q] & 31)) & 1u) g_nbr[d[q]] = 1;
      } else {
        long long e2 = i + 8; if (e2 > hi) e2 = hi;
        for (long long t = i; t < e2; t++) {
          int s, d;
          if (is64) {
            s = (int)((const long long*)edge)[t];
            d = (int)((const long long*)edge)[E + t];
          } else {
            s = ((const int*)edge)[t];
            d = ((const int*)edge)[E + t];
          }
          atomicAdd(&g_probs[d], w[t]);
          if ((sMask[s >> 5] >> (s & 31)) & 1u) g_nbr[d] = 1;
        }
      }
    }
  }
  gsync(2);

  // ================= two hops =================
  for (int h = 0; h < 2; h++) {
    unsigned kh0 = h ? kB0 : kA0, kh1 = h ? kB1 : kA1;

    // ---- build keys (candidate-skip; bit-exact gumbel) ----
    for (int n = gt; n < N_NODES; n += NTH) {
      unsigned long long kk = 0;
      if (g_nbr[n] && !g_retained[n]) {
        unsigned bits = pbits32(kh0, kh1, (unsigned)n);
        float ur = __uint_as_float((bits >> 9) | 0x3f800000u) - 1.0f;
        float u  = fmaxf(1.17549435e-38f, ur + 1.17549435e-38f);
        float g  = -logf(-logf(u));
        float v  = logf(g_probs[n]) + g;
        if (isfinite(v)) {
          unsigned b   = __float_as_uint(v);
          unsigned ord = b ^ ((b & 0x80000000u) ? 0xFFFFFFFFu : 0x80000000u);
          kk = (((unsigned long long)ord) << 32) | (0xFFFFFFFFu - (unsigned)n);
          atomicAdd(&g_hist[(unsigned)(kk >> 48)], 1u);
        }
      }
      g_keys[n] = kk;
    }
    gsync(3 + h * 4);

    // ---- threshold (block 0): suffix scan over 65536 digits ----
    if (bid == 0) {
      unsigned mysum = 0;
      #pragma unroll 8
      for (int b = tid * 64; b < tid * 64 + 64; b++) mysum += g_hist[b];
      part[tid] = mysum; __syncthreads();
      for (int off = 1; off < TPB; off <<= 1) {
        unsigned v = part[tid];
        if (tid + off < TPB) v += part[tid + off];
        __syncthreads(); part[tid] = v; __syncthreads();
      }
      unsigned total = part[0];
      unsigned need = (total < HOP_BUDGET) ? total : HOP_BUDGET;
      if (tid == 0 && need == 0) {
        g_ctrl.thrT = 0xFFFFFFFFu; g_ctrl.need2 = 0; g_ctrl.take_all = 0;
        g_ctrl.cand_n = 0;
      }
      if (need != 0) {
        unsigned S = part[tid];
        if (S >= need && S - mysum < need) {
          unsigned acc = S - mysum;
          for (int b = tid * 64 + 63; b >= tid * 64; b--) {
            unsigned hb = g_hist[b];
            if (acc + hb >= need) {
              g_ctrl.thrT = (unsigned)b;
              unsigned need2 = need - acc;
              g_ctrl.need2 = need2;
              g_ctrl.take_all = (need2 >= hb) ? 1u : 0u;
              g_ctrl.cand_n = 0;
              break;
            }
            acc += hb;
          }
        }
      }
    }
    gsync(4 + h * 4);

    // ---- scatter winners + collect boundary; re-zero hist ----
    {
      unsigned T = g_ctrl.thrT;
      unsigned take_all = g_ctrl.take_all;
      for (int n = gt; n < 65536; n += NTH) g_hist[n] = 0;
      for (int n = gt; n < N_NODES; n += NTH) {
        unsigned long long kk = g_keys[n];
        if (kk) {
          unsigned dg = (unsigned)(kk >> 48);
          if (dg > T) {
            g_retained[n] = 1;
          } else if (dg == T) {
            if (take_all) {
              g_retained[n] = 1;
            } else {
              unsigned pos = atomicAdd(&g_ctrl.cand_n, 1u);
              if (pos < CAND_CAP) g_cand[pos] = kk;
            }
          }
        }
      }
    }
    gsync(5 + h * 4);

    // ---- boundary refine (block 0): level-2 hist (bits 47:36) + rank ----
    if (bid == 0) {
      unsigned take_all = g_ctrl.take_all;
      unsigned need2 = g_ctrl.need2;
      if (!take_all && need2 != 0) {
        unsigned cn = g_ctrl.cand_n;
        int cnt = (int)((cn < CAND_CAP) ? cn : CAND_CAP);
        for (int b = tid; b < 4096; b += TPB) sB[b] = 0;
        if (tid == 0) s_scnt = 0;
        __syncthreads();
        for (int i = tid; i < cnt; i += TPB)
          atomicAdd(&sB[(unsigned)(g_cand[i] >> 36) & 0xFFFu], 1u);
        __syncthreads();

        unsigned mysum = 0;
        for (int b = tid * 4; b < tid * 4 + 4; b++) mysum += sB[b];
        part[tid] = mysum; __syncthreads();
        for (int off = 1; off < TPB; off <<= 1) {
          unsigned v = part[tid];
          if (tid + off < TPB) v += part[tid + off];
          __syncthreads(); part[tid] = v; __syncthreads();
        }
        unsigned S = part[tid];
        if (S >= need2 && S - mysum < need2) {
          unsigned acc = S - mysum; int T2 = tid * 4; unsigned n3 = need2;
          for (int b = tid * 4 + 3; b >= tid * 4; b--) {
            unsigned hb = sB[b];
            if (acc + hb >= need2) { T2 = b; n3 = need2 - acc; break; }
            acc += hb;
          }
          s_T2 = T2; s_need3 = n3;
        }
        __syncthreads();
        int T2 = s_T2;
        unsigned need3 = s_need3;

        for (int i = tid; i < cnt; i += TPB) {
          unsigned long long k = g_cand[i];
          int d2 = (int)((k >> 36) & 0xFFFu);
          if (d2 > T2) {
            g_retained[0xFFFFFFFFu - (unsigned)(k & 0xFFFFFFFFu)] = 1;
          } else if (d2 == T2) {
            unsigned p = atomicAdd(&s_scnt, 1u);
            if (p < 4096) sA[p] = k;
          }
        }
        __syncthreads();
        int c2 = (int)((s_scnt < 4096u) ? s_scnt : 4096u);
        for (int p = tid; p < c2; p += TPB) {
          unsigned long long myk = sA[p];
          int rank = 0;
          for (int i = 0; i < c2; i++) rank += (sA[i] > myk);
          if (rank < (int)need3)
            g_retained[0xFFFFFFFFu - (unsigned)(myk & 0xFFFFFFFFu)] = 1;
        }
      }
    }
    gsync(6 + h * 4);
  }

  // ================= output =================
  for (long long i = gt; i < out_size; i += NTH) {
    float v;
    if (out_size == 420000) {
      if (i < 20000)        v = (float)g_center_nodes[i];
      else if (i < 220000)  v = g_retained[i - 20000] ? 1.f : 0.f;
      else                  v = g_retained[i - 220000] ? g_probs[i - 220000] : 0.f;
    } else if (out_size == 400000) {
      if (i < 200000)       v = g_retained[i] ? 1.f : 0.f;
      else                  v = g_retained[i - 200000] ? g_probs[i - 200000] : 0.f;
    } else if (out_size == 200000) {
      v = g_retained[i] ? g_probs[i] : 0.f;
    } else if (out_size == 20000) {
      v = (float)g_center_nodes[i];
    } else {
      v = 0.f;
    }
    out[i] = v;
  }
}

// ---------------------------------------------------------------------------
extern "C" void kernel_launch(void* const* d_in, const int* in_sizes, int n_in,
                              void* d_out, int out_size) {
  const void* edge = d_in[0];
  const float* w = (const float*)d_in[1];
  long long E = (long long)in_sizes[0] / 2;

  static int smem_set = 0;
  const int SMEM = 69632 + 25008;
  if (!smem_set) {
    cudaFuncSetAttribute(k_all, cudaFuncAttributeMaxDynamicSharedMemorySize, SMEM);
    smem_set = 1;
  }
  k_all<<<GRID, TPB, SMEM>>>(edge, w, E, (float*)d_out, (long long)out_size);
}

// round 11
// speedup vs baseline: 1.9821x; 1.9675x over previous
#include <cuda_runtime.h>
#include <cstdint>

#define N_NODES     200000
#define N_CLS       10
#define IDS_PER_CLS 20000
#define CENTER_BUDGET 2000
#define HOP_BUDGET  16384
#define CAND_CAP    16384
#define CCAP        4096
#define NODE_BLOCKS 196     // 196*1024 >= 200000

struct Ctrl {
  unsigned keys[6];
  unsigned cand_n;
  unsigned need2;
  unsigned thrT;       // level-1 threshold digit (bits 63:48); 0xFFFFFFFF = none
  unsigned take_all;
  int      is64;
};

__device__ Ctrl               g_ctrl;
__device__ unsigned           g_done[4];
__device__ float              g_probs[N_NODES];
__device__ unsigned long long g_keys[N_NODES];
__device__ unsigned char      g_center[N_NODES];
__device__ unsigned char      g_retained[N_NODES];
__device__ unsigned char      g_nbr[N_NODES];
__device__ unsigned           g_hist[65536];
__device__ unsigned long long g_cand[CAND_CAP];
__device__ int                g_center_nodes[N_CLS * CENTER_BUDGET];

// ---------------------------------------------------------------------------
// threefry2x32 — matches JAX bit-for-bit (partitionable mode; validated)
// ---------------------------------------------------------------------------
__device__ __forceinline__ void tf2x32(unsigned k0, unsigned k1,
                                       unsigned x0, unsigned x1,
                                       unsigned &o0, unsigned &o1) {
  unsigned ks2 = k0 ^ k1 ^ 0x1BD11BDAu;
  x0 += k0; x1 += k1;
#define TFR(r) { x0 += x1; x1 = (x1 << (r)) | (x1 >> (32 - (r))); x1 ^= x0; }
  TFR(13) TFR(15) TFR(26) TFR(6)
  x0 += k1;  x1 += ks2 + 1u;
  TFR(17) TFR(29) TFR(16) TFR(24)
  x0 += ks2; x1 += k0 + 2u;
  TFR(13) TFR(15) TFR(26) TFR(6)
  x0 += k0;  x1 += k1 + 3u;
  TFR(17) TFR(29) TFR(16) TFR(24)
  x0 += k1;  x1 += ks2 + 4u;
  TFR(13) TFR(15) TFR(26) TFR(6)
  x0 += ks2; x1 += k0 + 5u;
#undef TFR
  o0 = x0; o1 = x1;
}
__device__ __forceinline__ unsigned pbits32(unsigned k0, unsigned k1, unsigned i) {
  unsigned o0, o1; tf2x32(k0, k1, 0u, i, o0, o1); return o0 ^ o1;
}
__device__ __forceinline__ unsigned long long pbits64(unsigned k0, unsigned k1, unsigned i) {
  unsigned o0, o1; tf2x32(k0, k1, 0u, i, o0, o1);
  return (((unsigned long long)o0) << 32) | o1;
}

extern __shared__ unsigned char s_raw[];

// ---------------------------------------------------------------------------
// Kernel 1: start + centers via counting-sort rank (bit-identical ranks).
// Block c owns class c. smem: skey u64[4096] | sjdx u32[4096] |
//                             cur u32[4096] (hist->cursor) | ebase u32[4096]
// ---------------------------------------------------------------------------
__global__ __launch_bounds__(1024) void k_centers_start(const void* edge, long long E) {
  unsigned long long* skey  = (unsigned long long*)s_raw;          // 32KB
  unsigned*           sjdx  = (unsigned*)(s_raw + 32768);          // 16KB
  unsigned*           cur   = (unsigned*)(s_raw + 49152);          // 16KB
  unsigned*           ebase = (unsigned*)(s_raw + 65536);          // 16KB
  __shared__ unsigned part[1024];
  __shared__ int      s_bad, s_T;

  int c = blockIdx.x, tid = threadIdx.x;
  int base = c * IDS_PER_CLS;

  // zero this block's node range + hist stripe
  for (int j = tid; j < IDS_PER_CLS; j += 1024) {
    int n = base + j;
    g_probs[n] = 0.f; g_center[n] = 0; g_retained[n] = 0; g_nbr[n] = 0;
  }
  for (int i = c * 1024 + tid; i < 65536; i += N_CLS * 1024) g_hist[i] = 0;

  // parallel dtype probe
  if (tid == 0) s_bad = 0;
  __syncthreads();
  {
    long long lim = (E < 128) ? E : 128;
    if (tid < 128 && (long long)tid < lim) {
      long long v = ((const long long*)edge)[tid];
      if (v < 0 || v >= N_NODES) atomicOr(&s_bad, 1);
    }
  }
  for (int b = tid; b < CCAP; b += 1024) cur[b] = 0;
  __syncthreads();
  const int is64 = s_bad ? 0 : 1;

  // publish keys/ctrl (block 0)
  unsigned kc0, kc1;
  tf2x32(0u, 42u, 0u, 0u, kc0, kc1);
  if (c == 0 && tid == 0) {
    unsigned o0, o1;
    g_ctrl.keys[0] = kc0; g_ctrl.keys[1] = kc1;
    tf2x32(0u, 42u, 0u, 1u, o0, o1); g_ctrl.keys[2] = o0; g_ctrl.keys[3] = o1;
    tf2x32(0u, 42u, 0u, 2u, o0, o1); g_ctrl.keys[4] = o0; g_ctrl.keys[5] = o1;
    g_ctrl.is64 = is64; g_ctrl.cand_n = 0;
    g_done[0] = 0; g_done[1] = 0; g_done[2] = 0; g_done[3] = 0;
  }

  // per-element uniform keys + 4096-bucket histogram
  for (int j = tid; j < IDS_PER_CLS; j += 1024) {
    unsigned m = (unsigned)(base + j);
    unsigned long long key; unsigned b;
    if (is64) {
      unsigned long long mant = pbits64(kc0, kc1, m) >> 12;   // u = mant*2^-52
      key = mant; b = (unsigned)(mant >> 40);
    } else {
      unsigned man = pbits32(kc0, kc1, m) >> 9;               // u = man*2^-23
      key = (((unsigned long long)man) << 32) | (unsigned)j;  // tie -> smaller j
      b = man >> 11;
    }
    g_keys[m] = key;
    atomicAdd(&cur[b], 1u);
  }
  __syncthreads();

  // exclusive per-bucket prefix + ascending threshold T
  unsigned c0 = cur[tid * 4 + 0], c1 = cur[tid * 4 + 1];
  unsigned c2 = cur[tid * 4 + 2], c3 = cur[tid * 4 + 3];
  unsigned mysum = c0 + c1 + c2 + c3;
  part[tid] = mysum; __syncthreads();
  for (int off = 1; off < 1024; off <<= 1) {
    unsigned v = part[tid];
    if (tid >= off) v += part[tid - off];
    __syncthreads(); part[tid] = v; __syncthreads();
  }
  unsigned P = part[tid];               // inclusive chunk sum
  unsigned chunkbase = P - mysum;       // exclusive
  ebase[tid * 4 + 0] = chunkbase;
  ebase[tid * 4 + 1] = chunkbase + c0;
  ebase[tid * 4 + 2] = chunkbase + c0 + c1;
  ebase[tid * 4 + 3] = chunkbase + c0 + c1 + c2;
  if (P >= CENTER_BUDGET && chunkbase < CENTER_BUDGET) {
    unsigned acc = chunkbase; int T = tid * 4 + 3;
    acc += c0; if (acc >= CENTER_BUDGET) { T = tid * 4 + 0; goto gotT; }
    acc += c1; if (acc >= CENTER_BUDGET) { T = tid * 4 + 1; goto gotT; }
    acc += c2; if (acc >= CENTER_BUDGET) { T = tid * 4 + 2; goto gotT; }
  gotT:
    s_T = T;
  }
  __syncthreads();
  int T = s_T;

  // cursors := ebase, then grouped scatter of candidates (bucket <= T)
  for (int q = tid; q < CCAP; q += 1024) cur[q] = ebase[q];
  __syncthreads();
  for (int j = tid; j < IDS_PER_CLS; j += 1024) {
    int m = base + j;
    unsigned long long key = g_keys[m];
    unsigned b = is64 ? (unsigned)(key >> 40) : (unsigned)(key >> 43);
    if ((int)b <= T) {
      unsigned pos = atomicAdd(&cur[b], 1u);
      skey[pos] = key; sjdx[pos] = (unsigned)j;
    }
  }
  __syncthreads();
  int cnt = (int)cur[T];                 // total stored (buckets <= T grouped)

  // exact rank = ebase[b] + within-bucket rank (bucket = key prefix)
  for (int p = tid; p < cnt; p += 1024) {
    unsigned long long k = skey[p];
    unsigned j = sjdx[p];
    unsigned b = is64 ? (unsigned)(k >> 40) : (unsigned)(k >> 43);
    unsigned st = ebase[b], en = cur[b];
    int rank = (int)st;
    for (unsigned i = st; i < en; i++) {
      unsigned long long ki = skey[i];
      unsigned ji = sjdx[i];
      rank += (ki < k) || (ki == k && ji < j);
    }
    if (rank < CENTER_BUDGET) {
      int node = base + (int)j;          // ids_per_cls == arange
      g_center_nodes[c * CENTER_BUDGET + rank] = node;
      g_center[node] = 1;
      g_retained[node] = 1;
    }
  }
}

// ---------------------------------------------------------------------------
// Kernel 2: fused edge pass (degree segment-sum + neighbor mask), 4/thread.
// Measured 95us standalone — keep verbatim.
// ---------------------------------------------------------------------------
__global__ __launch_bounds__(256) void k_edges(const void* __restrict__ edge,
                                               const float* __restrict__ w, long long E) {
  long long base = ((long long)blockIdx.x * 256 + threadIdx.x) * 4;
  if (base >= E) return;
  int is64 = g_ctrl.is64;
  if (base + 3 < E) {
    int s[4], d[4];
    if (is64) {
      const ulonglong2* ps = (const ulonglong2*)((const long long*)edge + base);
      const ulonglong2* pd = (const ulonglong2*)((const long long*)edge + E + base);
      ulonglong2 s01 = ps[0], s23 = ps[1];
      ulonglong2 d01 = pd[0], d23 = pd[1];
      s[0]=(int)s01.x; s[1]=(int)s01.y; s[2]=(int)s23.x; s[3]=(int)s23.y;
      d[0]=(int)d01.x; d[1]=(int)d01.y; d[2]=(int)d23.x; d[3]=(int)d23.y;
    } else {
      const int4* ps = (const int4*)((const int*)edge + base);
      const int4* pd = (const int4*)((const int*)edge + E + base);
      int4 sv = ps[0], dv = pd[0];
      s[0]=sv.x; s[1]=sv.y; s[2]=sv.z; s[3]=sv.w;
      d[0]=dv.x; d[1]=dv.y; d[2]=dv.z; d[3]=dv.w;
    }
    float4 wv = *(const float4*)(w + base);
    atomicAdd(&g_probs[d[0]], wv.x);
    atomicAdd(&g_probs[d[1]], wv.y);
    atomicAdd(&g_probs[d[2]], wv.z);
    atomicAdd(&g_probs[d[3]], wv.w);
    unsigned char c0 = g_center[s[0]], c1 = g_center[s[1]];
    unsigned char c2 = g_center[s[2]], c3 = g_center[s[3]];
    if (c0) g_nbr[d[0]] = 1;
    if (c1) g_nbr[d[1]] = 1;
    if (c2) g_nbr[d[2]] = 1;
    if (c3) g_nbr[d[3]] = 1;
  } else {
    for (long long i = base; i < E; i++) {
      int s, d;
      if (is64) {
        const long long* p = (const long long*)edge;
        s = (int)p[i]; d = (int)p[E + i];
      } else {
        const int* p = (const int*)edge;
        s = p[i]; d = p[E + i];
      }
      atomicAdd(&g_probs[d], w[i]);
      if (g_center[s]) g_nbr[d] = 1;
    }
  }
}

// ---------------------------------------------------------------------------
// Kernel 3 (x2): hop keys (candidate-skip) + lastblock threshold.
// ---------------------------------------------------------------------------
__global__ __launch_bounds__(1024) void k_build(int h) {
  __shared__ unsigned part[1024];
  __shared__ unsigned s_last;
  int n = blockIdx.x * blockDim.x + threadIdx.x;
  if (n < N_NODES) {
    unsigned long long kk = 0;
    if (g_nbr[n] && !g_retained[n]) {
      unsigned kh0 = g_ctrl.keys[2 + 2 * h], kh1 = g_ctrl.keys[3 + 2 * h];
      unsigned bits = pbits32(kh0, kh1, (unsigned)n);
      float ur = __uint_as_float((bits >> 9) | 0x3f800000u) - 1.0f;
      float u  = fmaxf(1.17549435e-38f, ur + 1.17549435e-38f);
      float g  = -logf(-logf(u));
      float v  = logf(g_probs[n]) + g;
      if (isfinite(v)) {
        unsigned b   = __float_as_uint(v);
        unsigned ord = b ^ ((b & 0x80000000u) ? 0xFFFFFFFFu : 0x80000000u);
        kk = (((unsigned long long)ord) << 32) | (0xFFFFFFFFu - (unsigned)n);
        atomicAdd(&g_hist[(unsigned)(kk >> 48)], 1u);
      }
    }
    g_keys[n] = kk;
  }

  __syncthreads();
  if (threadIdx.x == 0) {
    __threadfence();
    s_last = (atomicAdd(&g_done[2 * h], 1u) == gridDim.x - 1) ? 1u : 0u;
  }
  __syncthreads();
  if (!s_last) return;
  __threadfence();

  int tid = threadIdx.x;
  unsigned mysum = 0;
  #pragma unroll 8
  for (int b = tid * 64; b < tid * 64 + 64; b++) mysum += g_hist[b];
  part[tid] = mysum; __syncthreads();
  for (int off = 1; off < 1024; off <<= 1) {
    unsigned v = part[tid];
    if (tid + off < 1024) v += part[tid + off];
    __syncthreads(); part[tid] = v; __syncthreads();
  }
  unsigned total = part[0];
  unsigned need = (total < HOP_BUDGET) ? total : HOP_BUDGET;
  if (tid == 0 && need == 0) {
    g_ctrl.thrT = 0xFFFFFFFFu; g_ctrl.need2 = 0; g_ctrl.take_all = 0;
    g_ctrl.cand_n = 0;
  }
  if (need != 0) {
    unsigned S = part[tid];
    if (S >= need && S - mysum < need) {
      unsigned acc = S - mysum;
      for (int b = tid * 64 + 63; b >= tid * 64; b--) {
        unsigned hb = g_hist[b];
        if (acc + hb >= need) {
          g_ctrl.thrT = (unsigned)b;
          unsigned need2 = need - acc;
          g_ctrl.need2 = need2;
          g_ctrl.take_all = (need2 >= hb) ? 1u : 0u;
          g_ctrl.cand_n = 0;
          break;
        }
        acc += hb;
      }
    }
  }
}

// ---------------------------------------------------------------------------
// Kernel 4 (x2): scatter + boundary collect + hist re-zero; lastblock refine.
// ---------------------------------------------------------------------------
__global__ __launch_bounds__(1024) void k_scatter(int h) {
  __shared__ unsigned hist2[4096];
  __shared__ unsigned part[1024];
  __shared__ unsigned s_last, s_scnt;
  __shared__ int      s_T2;
  __shared__ unsigned s_need3;
  __shared__ unsigned long long skey[4096];

  int n = blockIdx.x * blockDim.x + threadIdx.x;
  unsigned T = g_ctrl.thrT;
  unsigned take_all = g_ctrl.take_all;
  if (n < 65536) g_hist[n] = 0;
  if (n < N_NODES) {
    unsigned long long kk = g_keys[n];
    if (kk) {
      unsigned dg = (unsigned)(kk >> 48);
      if (dg > T) {
        g_retained[n] = 1;
      } else if (dg == T) {
        if (take_all) {
          g_retained[n] = 1;
        } else {
          unsigned pos = atomicAdd(&g_ctrl.cand_n, 1u);
          if (pos < CAND_CAP) g_cand[pos] = kk;
        }
      }
    }
  }

  __syncthreads();
  if (threadIdx.x == 0) {
    __threadfence();
    s_last = (atomicAdd(&g_done[2 * h + 1], 1u) == gridDim.x - 1) ? 1u : 0u;
  }
  __syncthreads();
  if (!s_last) return;
  __threadfence();

  if (take_all) return;
  unsigned need2 = g_ctrl.need2;
  if (need2 == 0) return;
  unsigned cn = g_ctrl.cand_n;
  int cnt = (int)((cn < CAND_CAP) ? cn : CAND_CAP);
  int tid = threadIdx.x;

  for (int b = tid; b < 4096; b += 1024) hist2[b] = 0;
  if (tid == 0) s_scnt = 0;
  __syncthreads();
  for (int i = tid; i < cnt; i += 1024)
    atomicAdd(&hist2[(unsigned)(g_cand[i] >> 36) & 0xFFFu], 1u);
  __syncthreads();

  unsigned mysum = 0;
  for (int b = tid * 4; b < tid * 4 + 4; b++) mysum += hist2[b];
  part[tid] = mysum; __syncthreads();
  for (int off = 1; off < 1024; off <<= 1) {
    unsigned v = part[tid];
    if (tid + off < 1024) v += part[tid + off];
    __syncthreads(); part[tid] = v; __syncthreads();
  }
  unsigned S = part[tid];
  if (S >= need2 && S - mysum < need2) {
    unsigned acc = S - mysum; int T2 = tid * 4; unsigned n3 = need2;
    for (int b = tid * 4 + 3; b >= tid * 4; b--) {
      unsigned hb = hist2[b];
      if (acc + hb >= need2) { T2 = b; n3 = need2 - acc; break; }
      acc += hb;
    }
    s_T2 = T2; s_need3 = n3;
  }
  __syncthreads();
  int T2 = s_T2;
  unsigned need3 = s_need3;

  for (int i = tid; i < cnt; i += 1024) {
    unsigned long long k = g_cand[i];
    int d2 = (int)((k >> 36) & 0xFFFu);
    if (d2 > T2) {
      g_retained[0xFFFFFFFFu - (unsigned)(k & 0xFFFFFFFFu)] = 1;
    } else if (d2 == T2) {
      unsigned p = atomicAdd(&s_scnt, 1u);
      if (p < 4096) skey[p] = k;
    }
  }
  __syncthreads();
  int c2 = (int)((s_scnt < 4096u) ? s_scnt : 4096u);
  for (int p = tid; p < c2; p += 1024) {
    unsigned long long myk = skey[p];
    int rank = 0;
    for (int i = 0; i < c2; i++) rank += (skey[i] > myk);
    if (rank < (int)need3)
      g_retained[0xFFFFFFFFu - (unsigned)(myk & 0xFFFFFFFFu)] = 1;
  }
}

// ---------------------------------------------------------------------------
__global__ void k_out(float* __restrict__ out, long long out_size) {
  long long i = (long long)blockIdx.x * blockDim.x + threadIdx.x;
  if (i >= out_size) return;
  float v;
  if (out_size == 420000) {
    if (i < 20000)        v = (float)g_center_nodes[i];
    else if (i < 220000)  v = g_retained[i - 20000] ? 1.f : 0.f;
    else                  v = g_retained[i - 220000] ? g_probs[i - 220000] : 0.f;
  } else if (out_size == 400000) {
    if (i < 200000)       v = g_retained[i] ? 1.f : 0.f;
    else                  v = g_retained[i - 200000] ? g_probs[i - 200000] : 0.f;
  } else if (out_size == 200000) {
    v = g_retained[i] ? g_probs[i] : 0.f;
  } else if (out_size == 20000) {
    v = (float)g_center_nodes[i];
  } else {
    v = 0.f;
  }
  out[i] = v;
}

// ---------------------------------------------------------------------------
extern "C" void kernel_launch(void* const* d_in, const int* in_sizes, int n_in,
                              void* d_out, int out_size) {
  const void* edge = d_in[0];
  const float* w = (const float*)d_in[1];
  long long E = (long long)in_sizes[0] / 2;

  static int smem_set = 0;
  if (!smem_set) {
    cudaFuncSetAttribute(k_centers_start, cudaFuncAttributeMaxDynamicSharedMemorySize,
                         CCAP * 8 + CCAP * 4 + CCAP * 4 + CCAP * 4);
    smem_set = 1;
  }

  k_centers_start<<<N_CLS, 1024, CCAP * 8 + CCAP * 4 + CCAP * 4 + CCAP * 4>>>(edge, E);
  k_edges<<<(unsigned)((E + 1023) / 1024), 256>>>(edge, w, E);
  for (int h = 0; h < 2; h++) {
    k_build<<<NODE_BLOCKS, 1024>>>(h);
    k_scatter<<<NODE_BLOCKS, 1024>>>(h);
  }
  k_out<<<((long long)out_size + 255) / 256, 256>>>((float*)d_out, (long long)out_size);
}

// round 12
// speedup vs baseline: 2.0111x; 1.0147x over previous
#include <cuda_runtime.h>
#include <cstdint>

#define N_NODES     200000
#define N_CLS       10
#define IDS_PER_CLS 20000
#define CENTER_BUDGET 2000
#define HOP_BUDGET  16384
#define CAND_CAP    16384
#define CCAP        4096
#define HGRID       148
#define TPB         1024
#define HNTH        (HGRID * TPB)
#define GS          16

struct Ctrl {
  unsigned keys[6];
  unsigned cand_n;
  unsigned need2;
  unsigned thrT;
  unsigned take_all;
  int      is64;
};

__device__ Ctrl               g_ctrl;
__device__ unsigned           g_cnt[GS];    // gsync counters (self-resetting)
__device__ unsigned           g_flag[GS];   // gsync sense (monotonic across replays)
__device__ float              g_probs[N_NODES];
__device__ unsigned long long g_keys[N_NODES];
__device__ unsigned char      g_center[N_NODES];
__device__ unsigned char      g_retained[N_NODES];
__device__ unsigned char      g_nbr[N_NODES];
__device__ unsigned           g_hist[65536];
__device__ unsigned long long g_cand[CAND_CAP];
__device__ int                g_center_nodes[N_CLS * CENTER_BUDGET];

// ---------------------------------------------------------------------------
// threefry2x32 — matches JAX bit-for-bit (partitionable mode; validated)
// ---------------------------------------------------------------------------
__device__ __forceinline__ void tf2x32(unsigned k0, unsigned k1,
                                       unsigned x0, unsigned x1,
                                       unsigned &o0, unsigned &o1) {
  unsigned ks2 = k0 ^ k1 ^ 0x1BD11BDAu;
  x0 += k0; x1 += k1;
#define TFR(r) { x0 += x1; x1 = (x1 << (r)) | (x1 >> (32 - (r))); x1 ^= x0; }
  TFR(13) TFR(15) TFR(26) TFR(6)
  x0 += k1;  x1 += ks2 + 1u;
  TFR(17) TFR(29) TFR(16) TFR(24)
  x0 += ks2; x1 += k0 + 2u;
  TFR(13) TFR(15) TFR(26) TFR(6)
  x0 += k0;  x1 += k1 + 3u;
  TFR(17) TFR(29) TFR(16) TFR(24)
  x0 += k1;  x1 += ks2 + 4u;
  TFR(13) TFR(15) TFR(26) TFR(6)
  x0 += ks2; x1 += k0 + 5u;
#undef TFR
  o0 = x0; o1 = x1;
}
__device__ __forceinline__ unsigned pbits32(unsigned k0, unsigned k1, unsigned i) {
  unsigned o0, o1; tf2x32(k0, k1, 0u, i, o0, o1); return o0 ^ o1;
}
__device__ __forceinline__ unsigned long long pbits64(unsigned k0, unsigned k1, unsigned i) {
  unsigned o0, o1; tf2x32(k0, k1, 0u, i, o0, o1);
  return (((unsigned long long)o0) << 32) | o1;
}

// ---------------------------------------------------------------------------
// Replay-safe grid barrier (validated in R9/R10).
// ---------------------------------------------------------------------------
__device__ __forceinline__ void gsync(int i) {
  __syncthreads();
  if (threadIdx.x == 0) {
    __threadfence();
    unsigned f0 = atomicAdd(&g_flag[i], 0u);
    __threadfence();
    if (atomicAdd(&g_cnt[i], 1u) == HGRID - 1u) {
      g_cnt[i] = 0u;
      __threadfence();
      atomicAdd(&g_flag[i], 1u);
    } else {
      while (atomicAdd(&g_flag[i], 0u) == f0) __nanosleep(64);
    }
    __threadfence();
  }
  __syncthreads();
}

extern __shared__ unsigned char s_raw[];

// ---------------------------------------------------------------------------
// Kernel 1: start + centers (counting-sort rank; verbatim from R11, validated)
// smem: skey u64[4096] | sjdx u32[4096] | cur u32[4096] | ebase u32[4096]
// ---------------------------------------------------------------------------
__global__ __launch_bounds__(1024) void k_centers_start(const void* edge, long long E) {
  unsigned long long* skey  = (unsigned long long*)s_raw;          // 32KB
  unsigned*           sjdx  = (unsigned*)(s_raw + 32768);          // 16KB
  unsigned*           cur   = (unsigned*)(s_raw + 49152);          // 16KB
  unsigned*           ebase = (unsigned*)(s_raw + 65536);          // 16KB
  __shared__ unsigned part[1024];
  __shared__ int      s_bad, s_T;

  int c = blockIdx.x, tid = threadIdx.x;
  int base = c * IDS_PER_CLS;

  for (int j = tid; j < IDS_PER_CLS; j += 1024) {
    int n = base + j;
    g_probs[n] = 0.f; g_center[n] = 0; g_retained[n] = 0; g_nbr[n] = 0;
  }
  for (int i = c * 1024 + tid; i < 65536; i += N_CLS * 1024) g_hist[i] = 0;

  if (tid == 0) s_bad = 0;
  __syncthreads();
  {
    long long lim = (E < 128) ? E : 128;
    if (tid < 128 && (long long)tid < lim) {
      long long v = ((const long long*)edge)[tid];
      if (v < 0 || v >= N_NODES) atomicOr(&s_bad, 1);
    }
  }
  for (int b = tid; b < CCAP; b += 1024) cur[b] = 0;
  __syncthreads();
  const int is64 = s_bad ? 0 : 1;

  unsigned kc0, kc1;
  tf2x32(0u, 42u, 0u, 0u, kc0, kc1);
  if (c == 0 && tid == 0) {
    unsigned o0, o1;
    g_ctrl.keys[0] = kc0; g_ctrl.keys[1] = kc1;
    tf2x32(0u, 42u, 0u, 1u, o0, o1); g_ctrl.keys[2] = o0; g_ctrl.keys[3] = o1;
    tf2x32(0u, 42u, 0u, 2u, o0, o1); g_ctrl.keys[4] = o0; g_ctrl.keys[5] = o1;
    g_ctrl.is64 = is64; g_ctrl.cand_n = 0;
  }

  for (int j = tid; j < IDS_PER_CLS; j += 1024) {
    unsigned m = (unsigned)(base + j);
    unsigned long long key; unsigned b;
    if (is64) {
      unsigned long long mant = pbits64(kc0, kc1, m) >> 12;
      key = mant; b = (unsigned)(mant >> 40);
    } else {
      unsigned man = pbits32(kc0, kc1, m) >> 9;
      key = (((unsigned long long)man) << 32) | (unsigned)j;
      b = man >> 11;
    }
    g_keys[m] = key;
    atomicAdd(&cur[b], 1u);
  }
  __syncthreads();

  unsigned c0 = cur[tid * 4 + 0], c1 = cur[tid * 4 + 1];
  unsigned c2 = cur[tid * 4 + 2], c3 = cur[tid * 4 + 3];
  unsigned mysum = c0 + c1 + c2 + c3;
  part[tid] = mysum; __syncthreads();
  for (int off = 1; off < 1024; off <<= 1) {
    unsigned v = part[tid];
    if (tid >= off) v += part[tid - off];
    __syncthreads(); part[tid] = v; __syncthreads();
  }
  unsigned P = part[tid];
  unsigned chunkbase = P - mysum;
  ebase[tid * 4 + 0] = chunkbase;
  ebase[tid * 4 + 1] = chunkbase + c0;
  ebase[tid * 4 + 2] = chunkbase + c0 + c1;
  ebase[tid * 4 + 3] = chunkbase + c0 + c1 + c2;
  if (P >= CENTER_BUDGET && chunkbase < CENTER_BUDGET) {
    unsigned acc = chunkbase; int T = tid * 4 + 3;
    acc += c0; if (acc >= CENTER_BUDGET) { T = tid * 4 + 0; goto gotT; }
    acc += c1; if (acc >= CENTER_BUDGET) { T = tid * 4 + 1; goto gotT; }
    acc += c2; if (acc >= CENTER_BUDGET) { T = tid * 4 + 2; goto gotT; }
  gotT:
    s_T = T;
  }
  __syncthreads();
  int T = s_T;

  for (int q = tid; q < CCAP; q += 1024) cur[q] = ebase[q];
  __syncthreads();
  for (int j = tid; j < IDS_PER_CLS; j += 1024) {
    int m = base + j;
    unsigned long long key = g_keys[m];
    unsigned b = is64 ? (unsigned)(key >> 40) : (unsigned)(key >> 43);
    if ((int)b <= T) {
      unsigned pos = atomicAdd(&cur[b], 1u);
      skey[pos] = key; sjdx[pos] = (unsigned)j;
    }
  }
  __syncthreads();
  int cnt = (int)cur[T];

  for (int p = tid; p < cnt; p += 1024) {
    unsigned long long k = skey[p];
    unsigned j = sjdx[p];
    unsigned b = is64 ? (unsigned)(k >> 40) : (unsigned)(k >> 43);
    unsigned st = ebase[b], en = cur[b];
    int rank = (int)st;
    for (unsigned i = st; i < en; i++) {
      unsigned long long ki = skey[i];
      unsigned ji = sjdx[i];
      rank += (ki < k) || (ki == k && ji < j);
    }
    if (rank < CENTER_BUDGET) {
      int node = base + (int)j;
      g_center_nodes[c * CENTER_BUDGET + rank] = node;
      g_center[node] = 1;
      g_retained[node] = 1;
    }
  }
}

// ---------------------------------------------------------------------------
// Kernel 2: fused edge pass (verbatim; measured 95us standalone)
// ---------------------------------------------------------------------------
__global__ __launch_bounds__(256) void k_edges(const void* __restrict__ edge,
                                               const float* __restrict__ w, long long E) {
  long long base = ((long long)blockIdx.x * 256 + threadIdx.x) * 4;
  if (base >= E) return;
  int is64 = g_ctrl.is64;
  if (base + 3 < E) {
    int s[4], d[4];
    if (is64) {
      const ulonglong2* ps = (const ulonglong2*)((const long long*)edge + base);
      const ulonglong2* pd = (const ulonglong2*)((const long long*)edge + E + base);
      ulonglong2 s01 = ps[0], s23 = ps[1];
      ulonglong2 d01 = pd[0], d23 = pd[1];
      s[0]=(int)s01.x; s[1]=(int)s01.y; s[2]=(int)s23.x; s[3]=(int)s23.y;
      d[0]=(int)d01.x; d[1]=(int)d01.y; d[2]=(int)d23.x; d[3]=(int)d23.y;
    } else {
      const int4* ps = (const int4*)((const int*)edge + base);
      const int4* pd = (const int4*)((const int*)edge + E + base);
      int4 sv = ps[0], dv = pd[0];
      s[0]=sv.x; s[1]=sv.y; s[2]=sv.z; s[3]=sv.w;
      d[0]=dv.x; d[1]=dv.y; d[2]=dv.z; d[3]=dv.w;
    }
    float4 wv = *(const float4*)(w + base);
    atomicAdd(&g_probs[d[0]], wv.x);
    atomicAdd(&g_probs[d[1]], wv.y);
    atomicAdd(&g_probs[d[2]], wv.z);
    atomicAdd(&g_probs[d[3]], wv.w);
    unsigned char c0 = g_center[s[0]], c1 = g_center[s[1]];
    unsigned char c2 = g_center[s[2]], c3 = g_center[s[3]];
    if (c0) g_nbr[d[0]] = 1;
    if (c1) g_nbr[d[1]] = 1;
    if (c2) g_nbr[d[2]] = 1;
    if (c3) g_nbr[d[3]] = 1;
  } else {
    for (long long i = base; i < E; i++) {
      int s, d;
      if (is64) {
        const long long* p = (const long long*)edge;
        s = (int)p[i]; d = (int)p[E + i];
      } else {
        const int* p = (const int*)edge;
        s = p[i]; d = p[E + i];
      }
      atomicAdd(&g_probs[d], w[i]);
      if (g_center[s]) g_nbr[d] = 1;
    }
  }
}

// ---------------------------------------------------------------------------
// Kernel 3: persistent hops + output. 148 blocks (all co-resident).
// smem carve: skey u64[4096] 32KB | hist2 u32[4096] 16KB | part u32[1024] 4KB
// ---------------------------------------------------------------------------
__global__ __launch_bounds__(TPB, 1) void k_hops_out(float* __restrict__ out,
                                                     long long out_size) {
  unsigned long long* skey  = (unsigned long long*)s_raw;          // 32KB
  unsigned*           hist2 = (unsigned*)(s_raw + 32768);          // 16KB
  unsigned*           part  = (unsigned*)(s_raw + 49152);          // 4KB
  __shared__ unsigned s_scnt, s_need3;
  __shared__ int      s_T2;

  const int tid = threadIdx.x;
  const int bid = blockIdx.x;
  const int gt  = bid * TPB + tid;

  unsigned kA0, kA1, kB0, kB1;
  tf2x32(0u, 42u, 0u, 1u, kA0, kA1);   // k_h1
  tf2x32(0u, 42u, 0u, 2u, kB0, kB1);   // k_h2

  for (int h = 0; h < 2; h++) {
    unsigned kh0 = h ? kB0 : kA0, kh1 = h ? kB1 : kA1;

    // ---- build keys (candidate-skip; bit-exact gumbel, validated) ----
    for (int n = gt; n < N_NODES; n += HNTH) {
      unsigned long long kk = 0;
      if (g_nbr[n] && !g_retained[n]) {
        unsigned bits = pbits32(kh0, kh1, (unsigned)n);
        float ur = __uint_as_float((bits >> 9) | 0x3f800000u) - 1.0f;
        float u  = fmaxf(1.17549435e-38f, ur + 1.17549435e-38f);
        float g  = -logf(-logf(u));
        float v  = logf(g_probs[n]) + g;
        if (isfinite(v)) {
          unsigned b   = __float_as_uint(v);
          unsigned ord = b ^ ((b & 0x80000000u) ? 0xFFFFFFFFu : 0x80000000u);
          kk = (((unsigned long long)ord) << 32) | (0xFFFFFFFFu - (unsigned)n);
          atomicAdd(&g_hist[(unsigned)(kk >> 48)], 1u);
        }
      }
      g_keys[n] = kk;
    }
    gsync(h * 4 + 0);

    // ---- threshold (block 0): suffix scan over 65536 digits ----
    if (bid == 0) {
      unsigned mysum = 0;
      #pragma unroll 8
      for (int b = tid * 64; b < tid * 64 + 64; b++) mysum += g_hist[b];
      part[tid] = mysum; __syncthreads();
      for (int off = 1; off < TPB; off <<= 1) {
        unsigned v = part[tid];
        if (tid + off < TPB) v += part[tid + off];
        __syncthreads(); part[tid] = v; __syncthreads();
      }
      unsigned total = part[0];
      unsigned need = (total < HOP_BUDGET) ? total : HOP_BUDGET;
      if (tid == 0 && need == 0) {
        g_ctrl.thrT = 0xFFFFFFFFu; g_ctrl.need2 = 0; g_ctrl.take_all = 0;
        g_ctrl.cand_n = 0;
      }
      if (need != 0) {
        unsigned S = part[tid];
        if (S >= need && S - mysum < need) {
          unsigned acc = S - mysum;
          for (int b = tid * 64 + 63; b >= tid * 64; b--) {
            unsigned hb = g_hist[b];
            if (acc + hb >= need) {
              g_ctrl.thrT = (unsigned)b;
              unsigned need2 = need - acc;
              g_ctrl.need2 = need2;
              g_ctrl.take_all = (need2 >= hb) ? 1u : 0u;
              g_ctrl.cand_n = 0;
              break;
            }
            acc += hb;
          }
        }
      }
    }
    gsync(h * 4 + 1);

    // ---- scatter winners + collect boundary; re-zero hist ----
    {
      unsigned T = g_ctrl.thrT;
      unsigned take_all = g_ctrl.take_all;
      for (int n = gt; n < 65536; n += HNTH) g_hist[n] = 0;
      for (int n = gt; n < N_NODES; n += HNTH) {
        unsigned long long kk = g_keys[n];
        if (kk) {
          unsigned dg = (unsigned)(kk >> 48);
          if (dg > T) {
            g_retained[n] = 1;
          } else if (dg == T) {
            if (take_all) {
              g_retained[n] = 1;
            } else {
              unsigned pos = atomicAdd(&g_ctrl.cand_n, 1u);
              if (pos < CAND_CAP) g_cand[pos] = kk;
            }
          }
        }
      }
    }
    gsync(h * 4 + 2);

    // ---- boundary refine (block 0): level-2 hist (bits 47:36) + rank ----
    if (bid == 0) {
      unsigned take_all = g_ctrl.take_all;
      unsigned need2 = g_ctrl.need2;
      if (!take_all && need2 != 0) {
        unsigned cn = g_ctrl.cand_n;
        int cnt = (int)((cn < CAND_CAP) ? cn : CAND_CAP);
        for (int b = tid; b < 4096; b += TPB) hist2[b] = 0;
        if (tid == 0) s_scnt = 0;
        __syncthreads();
        for (int i = tid; i < cnt; i += TPB)
          atomicAdd(&hist2[(unsigned)(g_cand[i] >> 36) & 0xFFFu], 1u);
        __syncthreads();

        unsigned mysum = 0;
        for (int b = tid * 4; b < tid * 4 + 4; b++) mysum += hist2[b];
        part[tid] = mysum; __syncthreads();
        for (int off = 1; off < TPB; off <<= 1) {
          unsigned v = part[tid];
          if (tid + off < TPB) v += part[tid + off];
          __syncthreads(); part[tid] = v; __syncthreads();
        }
        unsigned S = part[tid];
        if (S >= need2 && S - mysum < need2) {
          unsigned acc = S - mysum; int T2 = tid * 4; unsigned n3 = need2;
          for (int b = tid * 4 + 3; b >= tid * 4; b--) {
            unsigned hb = hist2[b];
            if (acc + hb >= need2) { T2 = b; n3 = need2 - acc; break; }
            acc += hb;
          }
          s_T2 = T2; s_need3 = n3;
        }
        __syncthreads();
        int T2 = s_T2;
        unsigned need3 = s_need3;

        for (int i = tid; i < cnt; i += TPB) {
          unsigned long long k = g_cand[i];
          int d2 = (int)((k >> 36) & 0xFFFu);
          if (d2 > T2) {
            g_retained[0xFFFFFFFFu - (unsigned)(k & 0xFFFFFFFFu)] = 1;
          } else if (d2 == T2) {
            unsigned p = atomicAdd(&s_scnt, 1u);
            if (p < 4096) skey[p] = k;
          }
        }
        __syncthreads();
        int c2 = (int)((s_scnt < 4096u) ? s_scnt : 4096u);
        for (int p = tid; p < c2; p += TPB) {
          unsigned long long myk = skey[p];
          int rank = 0;
          for (int i = 0; i < c2; i++) rank += (skey[i] > myk);
          if (rank < (int)need3)
            g_retained[0xFFFFFFFFu - (unsigned)(myk & 0xFFFFFFFFu)] = 1;
        }
      }
    }
    gsync(h * 4 + 3);
  }

  // ---- output ----
  for (long long i = gt; i < out_size; i += HNTH) {
    float v;
    if (out_size == 420000) {
      if (i < 20000)        v = (float)g_center_nodes[i];
      else if (i < 220000)  v = g_retained[i - 20000] ? 1.f : 0.f;
      else                  v = g_retained[i - 220000] ? g_probs[i - 220000] : 0.f;
    } else if (out_size == 400000) {
      if (i < 200000)       v = g_retained[i] ? 1.f : 0.f;
      else                  v = g_retained[i - 200000] ? g_probs[i - 200000] : 0.f;
    } else if (out_size == 200000) {
      v = g_retained[i] ? g_probs[i] : 0.f;
    } else if (out_size == 20000) {
      v = (float)g_center_nodes[i];
    } else {
      v = 0.f;
    }
    out[i] = v;
  }
}

// ---------------------------------------------------------------------------
extern "C" void kernel_launch(void* const* d_in, const int* in_sizes, int n_in,
                              void* d_out, int out_size) {
  const void* edge = d_in[0];
  const float* w = (const float*)d_in[1];
  long long E = (long long)in_sizes[0] / 2;

  static int smem_set = 0;
  if (!smem_set) {
    cudaFuncSetAttribute(k_centers_start, cudaFuncAttributeMaxDynamicSharedMemorySize,
                         CCAP * 8 + 3 * CCAP * 4);
    cudaFuncSetAttribute(k_hops_out, cudaFuncAttributeMaxDynamicSharedMemorySize,
                         32768 + 16384 + 4096);
    smem_set = 1;
  }

  k_centers_start<<<N_CLS, 1024, CCAP * 8 + 3 * CCAP * 4>>>(edge, E);
  k_edges<<<(unsigned)((E + 1023) / 1024), 256>>>(edge, w, E);
  k_hops_out<<<HGRID, TPB, 32768 + 16384 + 4096>>>((float*)d_out, (long long)out_size);
}